// round 1
// baseline (speedup 1.0000x reference)
#include <cuda_runtime.h>

// WaveLetPooling: input (8, 512, 512, 64) fp32 NHWC.
// a = in[:,0::2,0::2,:], b = in[:,0::2,1::2,:], c = in[:,1::2,0::2,:], d = in[:,1::2,1::2,:]
// ll = .5(a+b+c+d); lh = .5(-a+b-c+d); hl = .5(-a-b+c+d); hh = .5(a-b-c+d)
// Output: [ll | lh | hl | hh], each (8, 256, 256, 64), concatenated in d_out.

#define N_  8u
#define H_  512u
#define W_  512u
#define C_  64u
#define HO  (H_/2u)     // 256
#define WO  (W_/2u)     // 256
#define C4  (C_/4u)     // 16 float4 per position
#define Q4  (N_*HO*WO*C4)  // float4 count per quadrant = 8,388,608

__global__ __launch_bounds__(256) void wavelet_pool_kernel(
    const float4* __restrict__ in, float4* __restrict__ out)
{
    unsigned tid = blockIdx.x * blockDim.x + threadIdx.x;
    // tid -> (n, ho, wo, c4): c4 in [0,16), wo in [0,256), ho in [0,256), n in [0,8)
    unsigned c4 = tid & 15u;
    unsigned wo = (tid >> 4) & 255u;
    unsigned ho = (tid >> 12) & 255u;
    unsigned n  = tid >> 20;

    // input float4 index: ((n*H + h)*W + w)*C4 + c4, with h=2*ho, w=2*wo
    unsigned ibase = ((n * H_ + 2u * ho) * W_ + 2u * wo) * C4 + c4;
    const unsigned ROW4 = W_ * C4;  // float4 per input row = 8192

    float4 a = in[ibase];
    float4 b = in[ibase + C4];
    float4 c = in[ibase + ROW4];
    float4 d = in[ibase + ROW4 + C4];

    float4 ll, lh, hl, hh;
    ll.x = 0.5f * ( a.x + b.x + c.x + d.x);
    ll.y = 0.5f * ( a.y + b.y + c.y + d.y);
    ll.z = 0.5f * ( a.z + b.z + c.z + d.z);
    ll.w = 0.5f * ( a.w + b.w + c.w + d.w);

    lh.x = 0.5f * (-a.x + b.x - c.x + d.x);
    lh.y = 0.5f * (-a.y + b.y - c.y + d.y);
    lh.z = 0.5f * (-a.z + b.z - c.z + d.z);
    lh.w = 0.5f * (-a.w + b.w - c.w + d.w);

    hl.x = 0.5f * (-a.x - b.x + c.x + d.x);
    hl.y = 0.5f * (-a.y - b.y + c.y + d.y);
    hl.z = 0.5f * (-a.z - b.z + c.z + d.z);
    hl.w = 0.5f * (-a.w - b.w + c.w + d.w);

    hh.x = 0.5f * ( a.x - b.x - c.x + d.x);
    hh.y = 0.5f * ( a.y - b.y - c.y + d.y);
    hh.z = 0.5f * ( a.z - b.z - c.z + d.z);
    hh.w = 0.5f * ( a.w - b.w - c.w + d.w);

    // output float4 index within a quadrant: ((n*HO + ho)*WO + wo)*C4 + c4
    unsigned o = ((n * HO + ho) * WO + wo) * C4 + c4;
    out[o]          = ll;
    out[o + Q4]     = lh;
    out[o + 2u*Q4]  = hl;
    out[o + 3u*Q4]  = hh;
}

extern "C" void kernel_launch(void* const* d_in, const int* in_sizes, int n_in,
                              void* d_out, int out_size)
{
    const float4* in  = (const float4*)d_in[0];
    float4*       out = (float4*)d_out;

    // total threads = one per output float4 per quadrant position = Q4
    const unsigned total = Q4;          // 8,388,608
    const unsigned block = 256;
    const unsigned grid  = total / block;  // 32768
    wavelet_pool_kernel<<<grid, block>>>(in, out);
}

// round 2
// speedup vs baseline: 1.0010x; 1.0010x over previous
#include <cuda_runtime.h>

// WaveLetPooling: input (8, 512, 512, 64) fp32 NHWC.
// Output: [ll | lh | hl | hh], each (8, 256, 256, 64), concatenated.
// Each thread handles TWO adjacent output wo positions (8 input float4 loads,
// 8 output float4 stores) to raise MLP and make per-warp loads cover a
// contiguous 1KB span per input row. Streaming hints (ldcs/stcs): no reuse.

#define N_  8u
#define H_  512u
#define W_  512u
#define C_  64u
#define HO  (H_/2u)       // 256
#define WO  (W_/2u)       // 256
#define C4  (C_/4u)       // 16 float4 per position
#define Q4  (N_*HO*WO*C4) // float4 per quadrant = 8,388,608

__device__ __forceinline__ float4 haar(const float4& a, const float4& b,
                                       const float4& c, const float4& d,
                                       float sa, float sb, float sc)
{
    float4 r;
    r.x = 0.5f * (sa * a.x + sb * b.x + sc * c.x + d.x);
    r.y = 0.5f * (sa * a.y + sb * b.y + sc * c.y + d.y);
    r.z = 0.5f * (sa * a.z + sb * b.z + sc * c.z + d.z);
    r.w = 0.5f * (sa * a.w + sb * b.w + sc * c.w + d.w);
    return r;
}

__global__ __launch_bounds__(256) void wavelet_pool_kernel(
    const float4* __restrict__ in, float4* __restrict__ out)
{
    unsigned tid = blockIdx.x * blockDim.x + threadIdx.x;
    // tid -> (n, ho, wo2, c4): c4 in [0,16), wo2 in [0,128), ho in [0,256), n in [0,8)
    unsigned c4  = tid & 15u;
    unsigned wo2 = (tid >> 4) & 127u;   // handles wo = 2*wo2 and 2*wo2+1
    unsigned ho  = (tid >> 11) & 255u;
    unsigned n   = tid >> 19;

    // input float4 index: ((n*H + 2*ho)*W + 4*wo2)*C4 + c4
    unsigned ibase = ((n * H_ + 2u * ho) * W_ + 4u * wo2) * C4 + c4;
    const unsigned ROW4 = W_ * C4;  // 8192 float4 per input row

    // 8 independent streaming loads, front-batched
    float4 a0 = __ldcs(in + ibase);
    float4 b0 = __ldcs(in + ibase + C4);
    float4 a1 = __ldcs(in + ibase + 2u * C4);
    float4 b1 = __ldcs(in + ibase + 3u * C4);
    float4 c0 = __ldcs(in + ibase + ROW4);
    float4 d0 = __ldcs(in + ibase + ROW4 + C4);
    float4 c1 = __ldcs(in + ibase + ROW4 + 2u * C4);
    float4 d1 = __ldcs(in + ibase + ROW4 + 3u * C4);

    // output float4 index within a quadrant: ((n*HO + ho)*WO + 2*wo2)*C4 + c4
    unsigned o = ((n * HO + ho) * WO + 2u * wo2) * C4 + c4;

    // position 0
    __stcs(out + o,            haar(a0, b0, c0, d0,  1.f,  1.f,  1.f));  // ll
    __stcs(out + o + Q4,       haar(a0, b0, c0, d0, -1.f,  1.f, -1.f));  // lh
    __stcs(out + o + 2u * Q4,  haar(a0, b0, c0, d0, -1.f, -1.f,  1.f));  // hl
    __stcs(out + o + 3u * Q4,  haar(a0, b0, c0, d0,  1.f, -1.f, -1.f));  // hh

    // position 1 (wo+1 -> output offset +C4)
    unsigned o1 = o + C4;
    __stcs(out + o1,           haar(a1, b1, c1, d1,  1.f,  1.f,  1.f));
    __stcs(out + o1 + Q4,      haar(a1, b1, c1, d1, -1.f,  1.f, -1.f));
    __stcs(out + o1 + 2u * Q4, haar(a1, b1, c1, d1, -1.f, -1.f,  1.f));
    __stcs(out + o1 + 3u * Q4, haar(a1, b1, c1, d1,  1.f, -1.f, -1.f));
}

extern "C" void kernel_launch(void* const* d_in, const int* in_sizes, int n_in,
                              void* d_out, int out_size)
{
    const float4* in  = (const float4*)d_in[0];
    float4*       out = (float4*)d_out;

    const unsigned total = Q4 / 2u;     // 4,194,304 threads
    const unsigned block = 256;
    const unsigned grid  = total / block;  // 16384
    wavelet_pool_kernel<<<grid, block>>>(in, out);
}